// round 8
// baseline (speedup 1.0000x reference)
#include <cuda_runtime.h>

#define THREADS 256
typedef unsigned long long u64;

// ---- prepped weight layouts (gmem scratch) ----
__device__ float w1q_d[3 * 32 * 128 * 4];   // [l][c4][h][4]  <- w1[l][h][c4*4+q]
__device__ float wP2_d[64 * 2 * 256];       // [hp][s][o]     <- grid_w[o][2*hp+s]
__device__ float w2q_d[3 * 32 * 128 * 4];   // [l][h4][c][4]  <- w2[l][c][h4*4+q]

__device__ __forceinline__ u64 fma2(u64 a, u64 b, u64 c) {
    u64 d; asm("fma.rn.f32x2 %0, %1, %2, %3;" : "=l"(d) : "l"(a), "l"(b), "l"(c)); return d;
}
__device__ __forceinline__ u64 add2(u64 a, u64 b) {
    u64 d; asm("add.rn.f32x2 %0, %1, %2;" : "=l"(d) : "l"(a), "l"(b)); return d;
}
__device__ __forceinline__ u64 mul2(u64 a, u64 b) {
    u64 d; asm("mul.rn.f32x2 %0, %1, %2;" : "=l"(d) : "l"(a), "l"(b)); return d;
}
__device__ __forceinline__ u64 pk(float a, float b) {
    u64 r; asm("mov.b64 %0, {%1, %2};" : "=l"(r) : "f"(a), "f"(b)); return r;
}
__device__ __forceinline__ void up(u64 v, float& a, float& b) {
    asm("mov.b64 {%0, %1}, %2;" : "=f"(a), "=f"(b) : "l"(v));
}
__device__ __forceinline__ float hsum2(u64 v) { float a, b; up(v, a, b); return a + b; }

__global__ void prep_kernel(const float* __restrict__ w1,
                            const float* __restrict__ gw,
                            const float* __restrict__ w2) {
    int idx = blockIdx.x * THREADS + threadIdx.x;
    if (idx < 49152) {
        int l = idx >> 14, r = idx & 16383;
        int c4 = r >> 9, r2 = r & 511, h = r2 >> 2, q = r2 & 3;
        w1q_d[idx] = w1[(l * 128 + h) * 128 + c4 * 4 + q];
    } else if (idx < 81920) {
        int k = idx - 49152;
        int hp = k >> 9, s = (k >> 8) & 1, o = k & 255;
        wP2_d[k] = gw[o * 128 + hp * 2 + s];
    } else if (idx < 131072) {
        int k = idx - 81920;
        int l = k >> 14, r = k & 16383;
        int h4 = r >> 9, r2 = r & 511, c = r2 >> 2, q = r2 & 3;
        w2q_d[k] = w2[(l * 128 + c) * 128 + h4 * 4 + q];
    }
}

// ---- smem float offsets (NB = 4 nodes per CTA) ----
// gP row stride = 50 u64 = 100 floats = 400 bytes (16B-aligned for LDS.128)
#define OFF_P    0        // 4x1152  packed/normalized p ; later h2
#define OFF_H    4608     // 4x1152  h1
#define OFF_GT   9216     // 6400    gP[hp][50 x u64] ; later g2N[a][130]
#define OFF_SG   15616    // 6192    sg[a][129] silu(gate) ; later u64 partials
#define OFF_TGT  21808    // 504     tg padded [a][12]
#define OFF_FGT  22312    // 504     fg transposed padded [a][12]
#define OFF_NW   22816    // 384
#define OFF_B1   23200    // 128
#define OFF_B2   23328    // 128
#define OFF_RED  23456    // 32
#define SMEM_FLOATS 23488

// linear1 run: weights loaded once per c4, fanned over CNT m's x 4 nodes
template<int CNT, bool BIAS>
__device__ __forceinline__ void lin1_run(int l, int m0, int h,
        const float* sP, float* sH, const float* s_b1) {
    const float4* wr = ((const float4*)w1q_d) + l * 4096 + h;
    u64 a0[CNT][4], a1[CNT][4];
    #pragma unroll
    for (int i = 0; i < CNT; ++i)
        #pragma unroll
        for (int nb = 0; nb < 4; ++nb) { a0[i][nb] = 0ull; a1[i][nb] = 0ull; }
    #pragma unroll 2
    for (int c4 = 0; c4 < 32; ++c4) {
        float4 w4 = wr[c4 * 128];
        u64 wxy = pk(w4.x, w4.y), wzw = pk(w4.z, w4.w);
        #pragma unroll
        for (int i = 0; i < CNT; ++i) {
            #pragma unroll
            for (int nb = 0; nb < 4; ++nb) {
                float4 p4 = ((const float4*)(sP + nb * 1152 + (m0 + i) * 128))[c4];
                a0[i][nb] = fma2(pk(p4.x, p4.y), wxy, a0[i][nb]);
                a1[i][nb] = fma2(pk(p4.z, p4.w), wzw, a1[i][nb]);
            }
        }
    }
    #pragma unroll
    for (int i = 0; i < CNT; ++i)
        #pragma unroll
        for (int nb = 0; nb < 4; ++nb) {
            float r = hsum2(a0[i][nb]) + hsum2(a1[i][nb]);
            if (BIAS) r += s_b1[h];
            sH[nb * 1152 + (m0 + i) * 128 + h] = r;
        }
}

// linear2 run: same structure, writes unpacked directly to gmem
template<int CNT, bool BIAS>
__device__ __forceinline__ void lin2_run(int l, int m0, int c,
        const float* sP, const float* s_b2,
        float* __restrict__ y, long long n0, int Nn) {
    const float4* wr = ((const float4*)w2q_d) + l * 4096 + c;
    u64 a0[CNT][4], a1[CNT][4];
    #pragma unroll
    for (int i = 0; i < CNT; ++i)
        #pragma unroll
        for (int nb = 0; nb < 4; ++nb) { a0[i][nb] = 0ull; a1[i][nb] = 0ull; }
    #pragma unroll 2
    for (int h4 = 0; h4 < 32; ++h4) {
        float4 w4 = wr[h4 * 128];
        u64 wxy = pk(w4.x, w4.y), wzw = pk(w4.z, w4.w);
        #pragma unroll
        for (int i = 0; i < CNT; ++i) {
            #pragma unroll
            for (int nb = 0; nb < 4; ++nb) {
                float4 p4 = ((const float4*)(sP + nb * 1152 + (m0 + i) * 128))[h4];
                a0[i][nb] = fma2(pk(p4.x, p4.y), wxy, a0[i][nb]);
                a1[i][nb] = fma2(pk(p4.z, p4.w), wzw, a1[i][nb]);
            }
        }
    }
    #pragma unroll
    for (int i = 0; i < CNT; ++i) {
        int m = m0 + i;
        int pidx;
        if (m == 0)      pidx = c;
        else if (m < 4)  pidx = 128 + c * 3 + (m - 1);
        else             pidx = 512 + c * 5 + (m - 4);
        #pragma unroll
        for (int nb = 0; nb < 4; ++nb) {
            float r = hsum2(a0[i][nb]) + hsum2(a1[i][nb]);
            if (BIAS) r += s_b2[c];
            long long node = n0 + nb; if (node >= Nn) node = Nn - 1;
            y[node * 1152 + pidx] = r;
        }
    }
}

__global__ __launch_bounds__(256, 2) void fused_kernel(
    const float* __restrict__ x,
    const float* __restrict__ nw,
    const float* __restrict__ b1,
    const float* __restrict__ gb,
    const float* __restrict__ b2,
    const float* __restrict__ tg,
    const float* __restrict__ fg,
    float* __restrict__ y, int Nn)
{
    extern __shared__ float sm[];
    float* sP    = sm + OFF_P;
    float* sH    = sm + OFF_H;
    float* gP    = sm + OFF_GT;   // [hp][50 u64]
    float* g2N   = sm + OFF_GT;   // [a][130] alias (after gP dead)
    float* sg    = sm + OFF_SG;   // [a][129] ; later u64 partials
    float* s_tgT = sm + OFF_TGT;
    float* s_fgT = sm + OFF_FGT;
    float* s_nw  = sm + OFF_NW;
    float* s_b1  = sm + OFF_B1;
    float* s_b2  = sm + OFF_B2;
    float* sRed  = sm + OFF_RED;

    const int tid = threadIdx.x;
    const long long n0 = (long long)blockIdx.x * 4;

    // stage small constants (padded [a][12] layouts for vector loads)
    for (int j = tid; j < 378; j += THREADS) {
        int a = j / 9, m = j - a * 9;
        s_tgT[a * 12 + m] = tg[j];            // tg is [a][m]
        s_fgT[a * 12 + m] = fg[m * 42 + a];   // fg is [m][a] -> transpose
    }
    for (int j = tid; j < 384; j += THREADS) s_nw[j] = nw[j];
    if (tid < 128) { s_b1[tid] = b1[tid]; s_b2[tid] = b2[tid]; }

    // ---- pack + sum of squares, 4 nodes ----
    float ss[4] = {0.f, 0.f, 0.f, 0.f};
    #pragma unroll
    for (int nb = 0; nb < 4; ++nb) {
        long long node = n0 + nb; if (node >= Nn) node = Nn - 1;
        const float4* xr4 = (const float4*)(x + node * 1152);
        float* sPn = sP + nb * 1152;
        for (int j4 = tid; j4 < 288; j4 += THREADS) {
            float4 v4 = xr4[j4];
            int jb = j4 * 4;
            float vv[4] = {v4.x, v4.y, v4.z, v4.w};
            #pragma unroll
            for (int k = 0; k < 4; ++k) {
                int j = jb + k;
                float v = vv[k];
                ss[nb] += v * v;
                int m, c;
                if (j < 128)      { m = 0; c = j; }
                else if (j < 512) { int u = j - 128; c = u / 3; m = 1 + (u - c * 3); }
                else              { int u = j - 512; c = u / 5; m = 4 + (u - c * 5); }
                sPn[m * 128 + c] = v;
            }
        }
    }
    #pragma unroll
    for (int nb = 0; nb < 4; ++nb) {
        float s = ss[nb];
        #pragma unroll
        for (int off = 16; off; off >>= 1) s += __shfl_xor_sync(0xffffffffu, s, off);
        if ((tid & 31) == 0) sRed[nb * 8 + (tid >> 5)] = s;
    }
    __syncthreads();
    {
        float inv[4];
        #pragma unroll
        for (int nb = 0; nb < 4; ++nb) {
            float tot = 0.f;
            #pragma unroll
            for (int w = 0; w < 8; ++w) tot += sRed[nb * 8 + w];
            inv[nb] = 1.0f / sqrtf(tot * (1.0f / 1152.0f) + 1e-6f);
        }
        for (int j = tid; j < 1152; j += THREADS) {
            int m = j >> 7, c = j & 127;
            int l = (m > 0) + (m > 3);
            float s = s_nw[l * 128 + c];
            #pragma unroll
            for (int nb = 0; nb < 4; ++nb) sP[nb * 1152 + j] *= inv[nb] * s;
        }
    }
    __syncthreads();

    // ---- SO3Linear #1, l-grouped, 4-node batched ----
    {
        const int h = tid & 127;
        if (tid < 128) {
            lin1_run<1, true >(0, 0, h, sP, sH, s_b1);
            lin1_run<3, false>(2, 4, h, sP, sH, s_b1);
        } else {
            lin1_run<3, false>(1, 1, h, sP, sH, s_b1);
            lin1_run<2, false>(2, 7, h, sP, sH, s_b1);
        }
    }
    __syncthreads();

    // ---- per-node grid pipeline ----
    for (int nb = 0; nb < 4; ++nb) {
        const float* sHn = sH + nb * 1152;
        float* sPn = sP + nb * 1152;

        // -- to S2 grid: thread owns fixed a, tg in registers, streams h1 pairs.
        //    Write the u64 h-pair accumulator directly into gP[hp][a]. --
        if (tid < 252) {
            int a = tid % 42, hp0 = tid / 42;
            const float4* tgp = (const float4*)(s_tgT + a * 12);
            float4 f0 = tgp[0], f1 = tgp[1];
            float f8 = s_tgT[a * 12 + 8];
            float tr[9] = {f0.x, f0.y, f0.z, f0.w, f1.x, f1.y, f1.z, f1.w, f8};
            const u64* hr0 = (const u64*)sHn;
            for (int hp = hp0; hp < 64; hp += 6) {
                const u64* hr = hr0 + hp;
                u64 acc = 0ull;
                #pragma unroll
                for (int m = 0; m < 9; ++m)
                    acc = fma2(hr[m * 64], pk(tr[m], tr[m]), acc);
                ((u64*)gP)[hp * 50 + a] = acc;
            }
        }
        __syncthreads();

        // -- SwiGLU GEMM: h-pair k-blocked, register-tiled outer product.
        //    Warps 2(a) x 4(o); thread 6a x 8o; per hp: 3 LDS.128 + 4 LDG.128 + 48 fma2. --
        {
            const int wid = tid >> 5, lane = tid & 31;
            const int wa = wid >> 2, wo = wid & 3;
            const int ag = lane >> 3, og = lane & 7;
            const int a0 = wa * 24 + ag * 6;      // even, in [0,48)
            const int o0 = wo * 64 + og * 8;      // in [0,256)

            u64 acc[6][4];
            #pragma unroll
            for (int i = 0; i < 6; ++i)
                #pragma unroll
                for (int j = 0; j < 4; ++j) acc[i][j] = 0ull;

            const float4* wbase = ((const float4*)wP2_d) + (o0 >> 2);  // + hp*128 (+64 for s=1)

            #pragma unroll 2
            for (int hp = 0; hp < 64; ++hp) {
                const float4* gvp = ((const float4*)(gP + hp * 100)) + (a0 >> 1);
                float4 G0 = gvp[0], G1 = gvp[1], G2 = gvp[2];
                const float4* wp = wbase + hp * 128;
                float4 W00 = wp[0],  W01 = wp[1];     // h0: o0..3, o4..7
                float4 W10 = wp[64], W11 = wp[65];    // h1: o0..3, o4..7
                u64 w0h0 = pk(W00.x, W00.y), w1h0 = pk(W00.z, W00.w);
                u64 w2h0 = pk(W01.x, W01.y), w3h0 = pk(W01.z, W01.w);
                u64 w0h1 = pk(W10.x, W10.y), w1h1 = pk(W10.z, W10.w);
                u64 w2h1 = pk(W11.x, W11.y), w3h1 = pk(W11.z, W11.w);
                float ga0[6] = {G0.x, G0.z, G1.x, G1.z, G2.x, G2.z};  // h0
                float ga1[6] = {G0.y, G0.w, G1.y, G1.w, G2.y, G2.w};  // h1
                #pragma unroll
                for (int i = 0; i < 6; ++i) {
                    u64 gd0 = pk(ga0[i], ga0[i]);
                    u64 gd1 = pk(ga1[i], ga1[i]);
                    acc[i][0] = fma2(gd0, w0h0, acc[i][0]);
                    acc[i][1] = fma2(gd0, w1h0, acc[i][1]);
                    acc[i][2] = fma2(gd0, w2h0, acc[i][2]);
                    acc[i][3] = fma2(gd0, w3h0, acc[i][3]);
                    acc[i][0] = fma2(gd1, w0h1, acc[i][0]);
                    acc[i][1] = fma2(gd1, w1h1, acc[i][1]);
                    acc[i][2] = fma2(gd1, w2h1, acc[i][2]);
                    acc[i][3] = fma2(gd1, w3h1, acc[i][3]);
                }
            }

            u64 gbp[4];
            {
                const u64* gb2 = ((const u64*)gb) + (o0 >> 1);
                #pragma unroll
                for (int j = 0; j < 4; ++j) gbp[j] = gb2[j];
            }
            #pragma unroll
            for (int i = 0; i < 6; ++i)
                #pragma unroll
                for (int j = 0; j < 4; ++j) acc[i][j] = add2(acc[i][j], gbp[j]);

            if (wo < 2) {
                // gate half: silu -> sg[a][129]
                #pragma unroll
                for (int i = 0; i < 6; ++i) {
                    float* row = sg + (a0 + i) * 129 + o0;
                    #pragma unroll
                    for (int j = 0; j < 4; ++j) {
                        float z0, z1; up(acc[i][j], z0, z1);
                        row[2 * j]     = z0 / (1.0f + __expf(-z0));
                        row[2 * j + 1] = z1 / (1.0f + __expf(-z1));
                    }
                }
            }
            __syncthreads();   // gP dead; sg ready
            if (wo >= 2) {
                const int hv = o0 - 128;
                #pragma unroll
                for (int i = 0; i < 6; ++i) {
                    const float* srow = sg + (a0 + i) * 129 + hv;
                    u64* drow = (u64*)(g2N + (a0 + i) * 130 + hv);
                    #pragma unroll
                    for (int j = 0; j < 4; ++j) {
                        u64 s2 = pk(srow[2 * j], srow[2 * j + 1]);
                        drow[j] = mul2(s2, acc[i][j]);
                    }
                }
            }
        }
        __syncthreads();

        // -- from S2 grid, phase 1: thread owns hp, stream g2 once over a-chunk --
        {
            const int hp = tid & 63, chunk = tid >> 6;
            const int abeg = (chunk == 0) ? 0 : (chunk == 1) ? 11 : (chunk == 2) ? 22 : 32;
            const int aend = (chunk == 0) ? 11 : (chunk == 1) ? 22 : (chunk == 2) ? 32 : 42;
            u64 am[9];
            #pragma unroll
            for (int m = 0; m < 9; ++m) am[m] = 0ull;
            const u64* g2 = ((const u64*)g2N) + hp;
            for (int a = abeg; a < aend; ++a) {
                u64 g = g2[a * 65];
                const float4* fp = (const float4*)(s_fgT + a * 12);
                float4 q0 = fp[0], q1 = fp[1];
                float q8 = s_fgT[a * 12 + 8];
                float fr[9] = {q0.x, q0.y, q0.z, q0.w, q1.x, q1.y, q1.z, q1.w, q8};
                #pragma unroll
                for (int m = 0; m < 9; ++m)
                    am[m] = fma2(g, pk(fr[m], fr[m]), am[m]);
            }
            u64* part = (u64*)sg;   // sg dead
            #pragma unroll
            for (int m = 0; m < 9; ++m)
                part[(chunk * 9 + m) * 64 + hp] = am[m];
        }
        __syncthreads();
        // -- phase 2: reduce 4 partials -> h2 into sP[nb] --
        {
            const u64* part = (const u64*)sg;
            for (int idx = tid; idx < 576; idx += THREADS) {
                int m = idx >> 6, hp = idx & 63;
                u64 s = add2(add2(part[(0 + m) * 64 + hp], part[(9 + m) * 64 + hp]),
                             add2(part[(18 + m) * 64 + hp], part[(27 + m) * 64 + hp]));
                ((u64*)(sPn + m * 128))[hp] = s;
            }
        }
        __syncthreads();
    }

    // ---- SO3Linear #2 + unpack store, l-grouped, 4-node batched ----
    {
        const int c = tid & 127;
        if (tid < 128) {
            lin2_run<1, true >(0, 0, c, sP, s_b2, y, n0, Nn);
            lin2_run<3, false>(2, 4, c, sP, s_b2, y, n0, Nn);
        } else {
            lin2_run<3, false>(1, 1, c, sP, s_b2, y, n0, Nn);
            lin2_run<2, false>(2, 7, c, sP, s_b2, y, n0, Nn);
        }
    }
}

extern "C" void kernel_launch(void* const* d_in, const int* in_sizes, int n_in,
                              void* d_out, int out_size) {
    const float* x  = (const float*)d_in[0];
    const float* nw = (const float*)d_in[1];
    const float* b1 = (const float*)d_in[3 - 2];  // placeholder avoided below
    (void)b1;
    const float* nw_ = nw; (void)nw_;
    const float* w1 = (const float*)d_in[2];
    const float* b1r = (const float*)d_in[3];
    const float* gw = (const float*)d_in[4];
    const float* gb = (const float*)d_in[5];
    const float* w2 = (const float*)d_in[6];
    const float* b2 = (const float*)d_in[7];
    const float* tg = (const float*)d_in[8];
    const float* fg = (const float*)d_in[9];
    float* y = (float*)d_out;

    int N = in_sizes[0] / 1152;
    int nblk = (N + 3) / 4;
    const int smem_bytes = SMEM_FLOATS * 4;

    prep_kernel<<<512, THREADS>>>(w1, gw, w2);

    cudaFuncSetAttribute(fused_kernel, cudaFuncAttributeMaxDynamicSharedMemorySize,
                         smem_bytes);
    fused_kernel<<<nblk, THREADS, smem_bytes>>>(x, nw, b1r, gb, b2, tg, fg, y, N);
}

// round 12
// speedup vs baseline: 1.1057x; 1.1057x over previous
#include <cuda_runtime.h>

#define THREADS 512
typedef unsigned long long u64;
typedef unsigned int u32;

// ---- prepped weight layouts (gmem scratch) ----
__device__ float w1q_d[3 * 32 * 128 * 4];   // [l][c4][h][4]  <- w1[l][h][c4*4+q]
__device__ float w2q_d[3 * 32 * 128 * 4];   // [l][h4][c][4]  <- w2[l][c][h4*4+q]
__device__ float gwQ_d[32768];              // [hp][s][jb][4] = {gw[2jb],gw[2jb+1],gw[128+2jb],gw[129+2jb]} @ h=2hp+s

__device__ __forceinline__ u64 fma2(u64 a, u64 b, u64 c) {
    u64 d; asm("fma.rn.f32x2 %0, %1, %2, %3;" : "=l"(d) : "l"(a), "l"(b), "l"(c)); return d;
}
__device__ __forceinline__ u64 add2(u64 a, u64 b) {
    u64 d; asm("add.rn.f32x2 %0, %1, %2;" : "=l"(d) : "l"(a), "l"(b)); return d;
}
__device__ __forceinline__ u64 pk(float a, float b) {
    u64 r; asm("mov.b64 %0, {%1, %2};" : "=l"(r) : "f"(a), "f"(b)); return r;
}
__device__ __forceinline__ void up(u64 v, float& a, float& b) {
    asm("mov.b64 {%0, %1}, %2;" : "=f"(a), "=f"(b) : "l"(v));
}
__device__ __forceinline__ float hsum2(u64 v) { float a, b; up(v, a, b); return a + b; }

__global__ void prep_kernel(const float* __restrict__ w1,
                            const float* __restrict__ gw,
                            const float* __restrict__ w2) {
    int idx = blockIdx.x * 256 + threadIdx.x;
    if (idx < 49152) {
        int l = idx >> 14, r = idx & 16383;
        int c4 = r >> 9, r2 = r & 511, h = r2 >> 2, q = r2 & 3;
        w1q_d[idx] = w1[(l * 128 + h) * 128 + c4 * 4 + q];
    } else if (idx < 98304) {
        int k = idx - 49152;
        int l = k >> 14, r = k & 16383;
        int h4 = r >> 9, r2 = r & 511, c = r2 >> 2, q = r2 & 3;
        w2q_d[k] = w2[(l * 128 + c) * 128 + h4 * 4 + q];
    } else if (idx < 131072) {
        int k = idx - 98304;
        int hp = k >> 9, s = (k >> 8) & 1, jb = (k >> 2) & 63, q = k & 3;
        int o = (q < 2) ? (2 * jb + q) : (128 + 2 * jb + (q - 2));
        gwQ_d[k] = gw[o * 128 + 2 * hp + s];
    }
}

// ---- smem byte offsets (one 512-thread CTA / SM, persistent) ----
#define SM_WQ    0         // 131072  SwiGLU weights [hp][s][jb][4]
#define SM_SP    131072    // 18432   4 x 1152 f : packed/normalized p ; later h2
#define SM_SH    149504    // 18432   4 x 1152 f : h1
#define SM_GP    167936    // 25600   gP[hp][50 u64]
#define SM_G2    193536    // 24960   g2N[48][65 u64]
#define SM_TGT   218496    // 504 f
#define SM_FGT   220512    // 504 f
#define SM_NW    222528    // 384 f
#define SM_B1    224064    // 128 f
#define SM_B2    224576    // 128 f
#define SM_RED   225088    // 64 f
#define SM_TOTAL 225344

template<int CNT, bool BIAS>
__device__ __forceinline__ void lin1_run(int l, int m0, int h,
        const float* sP, float* sH, const float* s_b1) {
    const float4* wr = ((const float4*)w1q_d) + l * 4096 + h;
    u64 a0[CNT][4], a1[CNT][4];
    #pragma unroll
    for (int i = 0; i < CNT; ++i)
        #pragma unroll
        for (int nb = 0; nb < 4; ++nb) { a0[i][nb] = 0ull; a1[i][nb] = 0ull; }
    #pragma unroll 2
    for (int c4 = 0; c4 < 32; ++c4) {
        float4 w4 = wr[c4 * 128];
        u64 wxy = pk(w4.x, w4.y), wzw = pk(w4.z, w4.w);
        #pragma unroll
        for (int i = 0; i < CNT; ++i)
            #pragma unroll
            for (int nb = 0; nb < 4; ++nb) {
                float4 p4 = ((const float4*)(sP + nb * 1152 + (m0 + i) * 128))[c4];
                a0[i][nb] = fma2(pk(p4.x, p4.y), wxy, a0[i][nb]);
                a1[i][nb] = fma2(pk(p4.z, p4.w), wzw, a1[i][nb]);
            }
    }
    #pragma unroll
    for (int i = 0; i < CNT; ++i)
        #pragma unroll
        for (int nb = 0; nb < 4; ++nb) {
            float r = hsum2(a0[i][nb]) + hsum2(a1[i][nb]);
            if (BIAS) r += s_b1[h];
            sH[nb * 1152 + (m0 + i) * 128 + h] = r;
        }
}

template<int CNT, bool BIAS>
__device__ __forceinline__ void lin2_run(int l, int m0, int c,
        const float* sP, const float* s_b2,
        float* __restrict__ y, long long n0, int Nn) {
    const float4* wr = ((const float4*)w2q_d) + l * 4096 + c;
    u64 a0[CNT][4], a1[CNT][4];
    #pragma unroll
    for (int i = 0; i < CNT; ++i)
        #pragma unroll
        for (int nb = 0; nb < 4; ++nb) { a0[i][nb] = 0ull; a1[i][nb] = 0ull; }
    #pragma unroll 2
    for (int h4 = 0; h4 < 32; ++h4) {
        float4 w4 = wr[h4 * 128];
        u64 wxy = pk(w4.x, w4.y), wzw = pk(w4.z, w4.w);
        #pragma unroll
        for (int i = 0; i < CNT; ++i)
            #pragma unroll
            for (int nb = 0; nb < 4; ++nb) {
                float4 p4 = ((const float4*)(sP + nb * 1152 + (m0 + i) * 128))[h4];
                a0[i][nb] = fma2(pk(p4.x, p4.y), wxy, a0[i][nb]);
                a1[i][nb] = fma2(pk(p4.z, p4.w), wzw, a1[i][nb]);
            }
    }
    #pragma unroll
    for (int i = 0; i < CNT; ++i) {
        int m = m0 + i;
        int pidx;
        if (m == 0)      pidx = c;
        else if (m < 4)  pidx = 128 + c * 3 + (m - 1);
        else             pidx = 512 + c * 5 + (m - 4);
        #pragma unroll
        for (int nb = 0; nb < 4; ++nb) {
            float r = hsum2(a0[i][nb]) + hsum2(a1[i][nb]);
            if (BIAS) r += s_b2[c];
            long long node = n0 + nb; if (node >= Nn) node = Nn - 1;
            y[node * 1152 + pidx] = r;
        }
    }
}

__global__ __launch_bounds__(512, 1) void fused_kernel(
    const float* __restrict__ x,
    const float* __restrict__ nw,
    const float* __restrict__ b1,
    const float* __restrict__ gb,
    const float* __restrict__ b2,
    const float* __restrict__ tg,
    const float* __restrict__ fg,
    float* __restrict__ y, int Nn, int ntiles)
{
    extern __shared__ char smx[];
    float* sWQ   = (float*)(smx + SM_WQ);
    float* sP    = (float*)(smx + SM_SP);
    float* sH    = (float*)(smx + SM_SH);
    float* gP    = (float*)(smx + SM_GP);
    float* g2f   = (float*)(smx + SM_G2);
    float* s_tgT = (float*)(smx + SM_TGT);
    float* s_fgT = (float*)(smx + SM_FGT);
    float* s_nw  = (float*)(smx + SM_NW);
    float* s_b1  = (float*)(smx + SM_B1);
    float* s_b2  = (float*)(smx + SM_B2);
    float* sRed  = (float*)(smx + SM_RED);

    const int tid = threadIdx.x;
    const int wid = tid >> 5, lane = tid & 31;

    // SwiGLU coords: warps 2(a) x 8(jb); thread 6a x 1 o-pair-column (gate+value)
    const int s_a0 = (wid >> 3) * 24 + (lane >> 3) * 6;   // [0,48), even
    const int s_jb = (wid & 7) * 8 + (lane & 7);          // [0,64)
    const u64 gbg = pk(__ldg(gb + 2 * s_jb), __ldg(gb + 2 * s_jb + 1));
    const u64 gbv = pk(__ldg(gb + 128 + 2 * s_jb), __ldg(gb + 128 + 2 * s_jb + 1));
    // toGrid coords
    const int t_a = (tid < 504) ? (tid % 42) : 0;
    const int t_hp0 = (tid < 504) ? (tid / 42) : 64;

    // stage constants + resident SwiGLU weights (once per CTA)
    for (int j = tid; j < 378; j += THREADS) {
        int a = j / 9, m = j - a * 9;
        s_tgT[a * 12 + m] = tg[j];
        s_fgT[a * 12 + m] = fg[m * 42 + a];
    }
    for (int j = tid; j < 384; j += THREADS) s_nw[j] = nw[j];
    if (tid < 128) { s_b1[tid] = b1[tid]; s_b2[tid] = b2[tid]; }
    {
        const float4* src = (const float4*)gwQ_d;
        float4* dst = (float4*)sWQ;
        for (int j = tid; j < 8192; j += THREADS) dst[j] = src[j];
    }
    __syncthreads();

    float tr[9];
    {
        const float4* tgp = (const float4*)(s_tgT + t_a * 12);
        float4 f0 = tgp[0], f1 = tgp[1];
        tr[0] = f0.x; tr[1] = f0.y; tr[2] = f0.z; tr[3] = f0.w;
        tr[4] = f1.x; tr[5] = f1.y; tr[6] = f1.z; tr[7] = f1.w;
        tr[8] = s_tgT[t_a * 12 + 8];
    }

    for (int tile = blockIdx.x; tile < ntiles; tile += gridDim.x) {
        const long long n0 = (long long)tile * 4;

        // ---- pack + sum of squares, 4 nodes ----
        float ss[4] = {0.f, 0.f, 0.f, 0.f};
        #pragma unroll
        for (int nb = 0; nb < 4; ++nb) {
            long long node = n0 + nb; if (node >= Nn) node = Nn - 1;
            const float4* xr4 = (const float4*)(x + node * 1152);
            float* sPn = sP + nb * 1152;
            for (int j4 = tid; j4 < 288; j4 += THREADS) {
                float4 v4 = xr4[j4];
                int jb = j4 * 4;
                float vv[4] = {v4.x, v4.y, v4.z, v4.w};
                #pragma unroll
                for (int k = 0; k < 4; ++k) {
                    int j = jb + k;
                    float v = vv[k];
                    ss[nb] += v * v;
                    int m, c;
                    if (j < 128)      { m = 0; c = j; }
                    else if (j < 512) { int u = j - 128; c = u / 3; m = 1 + (u - c * 3); }
                    else              { int u = j - 512; c = u / 5; m = 4 + (u - c * 5); }
                    sPn[m * 128 + c] = v;
                }
            }
        }
        #pragma unroll
        for (int nb = 0; nb < 4; ++nb) {
            float s = ss[nb];
            #pragma unroll
            for (int off = 16; off; off >>= 1) s += __shfl_xor_sync(0xffffffffu, s, off);
            if (lane == 0) sRed[nb * 16 + wid] = s;
        }
        __syncthreads();
        {
            float inv[4];
            #pragma unroll
            for (int nb = 0; nb < 4; ++nb) {
                float tot = 0.f;
                #pragma unroll
                for (int w = 0; w < 16; ++w) tot += sRed[nb * 16 + w];
                inv[nb] = 1.0f / sqrtf(tot * (1.0f / 1152.0f) + 1e-6f);
            }
            for (int j = tid; j < 1152; j += THREADS) {
                int m = j >> 7, c = j & 127;
                int l = (m > 0) + (m > 3);
                float s = s_nw[l * 128 + c];
                #pragma unroll
                for (int nb = 0; nb < 4; ++nb) sP[nb * 1152 + j] *= inv[nb] * s;
            }
        }
        __syncthreads();

        // ---- SO3Linear #1 ----
        {
            const int h = tid & 127, sel = tid >> 7;
            if (sel == 0)      { lin1_run<1, true >(0, 0, h, sP, sH, s_b1);
                                 lin1_run<1, false>(2, 4, h, sP, sH, s_b1); }
            else if (sel == 1) { lin1_run<2, false>(1, 1, h, sP, sH, s_b1); }
            else if (sel == 2) { lin1_run<1, false>(1, 3, h, sP, sH, s_b1);
                                 lin1_run<1, false>(2, 5, h, sP, sH, s_b1); }
            else               { lin1_run<3, false>(2, 6, h, sP, sH, s_b1); }
        }
        __syncthreads();

        // ---- per-node grid pipeline ----
        #pragma unroll 1
        for (int nb = 0; nb < 4; ++nb) {
            // -- toGrid: gP[hp][a] = u64 h-pair --
            {
                const u64* hr0 = (const u64*)(sH + nb * 1152);
                for (int hp = t_hp0; hp < 64; hp += 12) {
                    const u64* hr = hr0 + hp;
                    u64 acc = 0ull;
                    #pragma unroll
                    for (int m = 0; m < 9; ++m)
                        acc = fma2(hr[m * 64], pk(tr[m], tr[m]), acc);
                    ((u64*)gP)[hp * 50 + t_a] = acc;
                }
            }
            __syncthreads();

            // -- SwiGLU: smem-resident weights, thread-local gating --
            {
                u64 zg[6], zv[6];
                #pragma unroll
                for (int i = 0; i < 6; ++i) { zg[i] = 0ull; zv[i] = 0ull; }
                const float4* wq0 = ((const float4*)sWQ) + s_jb;
                const float4* wq1 = wq0 + 64;
                #pragma unroll 2
                for (int hp = 0; hp < 64; ++hp) {
                    const float4* gvp = (const float4*)(gP + hp * 100) + (s_a0 >> 1);
                    float4 G0 = gvp[0], G1 = gvp[1], G2 = gvp[2];
                    float4 q0 = wq0[hp * 128];
                    float4 q1 = wq1[hp * 128];
                    u64 wg0 = pk(q0.x, q0.y), wv0 = pk(q0.z, q0.w);
                    u64 wg1 = pk(q1.x, q1.y), wv1 = pk(q1.z, q1.w);
                    float ga0[6] = {G0.x, G0.z, G1.x, G1.z, G2.x, G2.z};
                    float ga1[6] = {G0.y, G0.w, G1.y, G1.w, G2.y, G2.w};
                    #pragma unroll
                    for (int i = 0; i < 6; ++i) {
                        u64 d0 = pk(ga0[i], ga0[i]);
                        u64 d1 = pk(ga1[i], ga1[i]);
                        zg[i] = fma2(d0, wg0, zg[i]);
                        zv[i] = fma2(d0, wv0, zv[i]);
                        zg[i] = fma2(d1, wg1, zg[i]);
                        zv[i] = fma2(d1, wv1, zv[i]);
                    }
                }
                #pragma unroll
                for (int i = 0; i < 6; ++i) {
                    u64 zgb = add2(zg[i], gbg);
                    u64 zvb = add2(zv[i], gbv);
                    float g0, g1, v0, v1;
                    up(zgb, g0, g1); up(zvb, v0, v1);
                    float r0 = (g0 / (1.0f + __expf(-g0))) * v0;
                    float r1 = (g1 / (1.0f + __expf(-g1))) * v1;
                    ((u64*)g2f)[(s_a0 + i) * 65 + s_jb] = pk(r0, r1);
                }
            }
            __syncthreads();

            // -- fromGrid: thread owns (hp, m-pair) --
            if (tid < 320) {
                const int hp = tid & 63, mp = tid >> 6;
                u64 am0 = 0ull, am1 = 0ull;
                const u64* g2 = ((const u64*)g2f) + hp;
                for (int a = 0; a < 42; ++a) {
                    u64 g = g2[a * 65];
                    u64 fpair = *(const u64*)(s_fgT + a * 12 + 2 * mp);
                    float f0, f1; up(fpair, f0, f1);
                    am0 = fma2(g, pk(f0, f0), am0);
                    if (mp < 4) am1 = fma2(g, pk(f1, f1), am1);
                }
                float* sPn = sP + nb * 1152;
                ((u64*)(sPn + (2 * mp) * 128))[hp] = am0;
                if (mp < 4) ((u64*)(sPn + (2 * mp + 1) * 128))[hp] = am1;
            }
            __syncthreads();
        }

        // ---- SO3Linear #2 + unpack store ----
        {
            const int c = tid & 127, sel = tid >> 7;
            if (sel == 0)      { lin2_run<1, true >(0, 0, c, sP, s_b2, y, n0, Nn);
                                 lin2_run<1, false>(2, 4, c, sP, s_b2, y, n0, Nn); }
            else if (sel == 1) { lin2_run<2, false>(1, 1, c, sP, s_b2, y, n0, Nn); }
            else if (sel == 2) { lin2_run<1, false>(1, 3, c, sP, s_b2, y, n0, Nn);
                                 lin2_run<1, false>(2, 5, c, sP, s_b2, y, n0, Nn); }
            else               { lin2_run<3, false>(2, 6, c, sP, s_b2, y, n0, Nn); }
        }
        __syncthreads();
    }
}

extern "C" void kernel_launch(void* const* d_in, const int* in_sizes, int n_in,
                              void* d_out, int out_size) {
    const float* x  = (const float*)d_in[0];
    const float* nw = (const float*)d_in[1];
    const float* w1 = (const float*)d_in[2];
    const float* b1 = (const float*)d_in[3];
    const float* gw = (const float*)d_in[4];
    const float* gb = (const float*)d_in[5];
    const float* w2 = (const float*)d_in[6];
    const float* b2 = (const float*)d_in[7];
    const float* tg = (const float*)d_in[8];
    const float* fg = (const float*)d_in[9];
    float* y = (float*)d_out;

    int N = in_sizes[0] / 1152;
    int ntiles = (N + 3) / 4;
    int grid = ntiles < 148 ? ntiles : 148;

    prep_kernel<<<512, 256>>>(w1, gw, w2);

    cudaFuncSetAttribute(fused_kernel, cudaFuncAttributeMaxDynamicSharedMemorySize,
                         SM_TOTAL);
    fused_kernel<<<grid, THREADS, SM_TOTAL>>>(x, nw, b1, gb, b2, tg, fg, y, N, ntiles);
}

// round 13
// speedup vs baseline: 1.1385x; 1.0297x over previous
#include <cuda_runtime.h>

#define THREADS 512
typedef unsigned long long u64;
typedef unsigned int u32;

// ---- prepped weight layouts (gmem scratch) ----
__device__ float w1q_d[3 * 32 * 128 * 4];   // [l][c4][h][4]  <- w1[l][h][c4*4+q]
__device__ float w2q_d[3 * 32 * 128 * 4];   // [l][h4][c][4]  <- w2[l][c][h4*4+q]
__device__ float gwQ_d[32768];              // [hp][s][jb][4] = {gw[2jb],gw[2jb+1],gw[128+2jb],gw[129+2jb]} @ h=2hp+s

__device__ __forceinline__ u64 fma2(u64 a, u64 b, u64 c) {
    u64 d; asm("fma.rn.f32x2 %0, %1, %2, %3;" : "=l"(d) : "l"(a), "l"(b), "l"(c)); return d;
}
__device__ __forceinline__ u64 add2(u64 a, u64 b) {
    u64 d; asm("add.rn.f32x2 %0, %1, %2;" : "=l"(d) : "l"(a), "l"(b)); return d;
}
__device__ __forceinline__ u64 pk(float a, float b) {
    u64 r; asm("mov.b64 %0, {%1, %2};" : "=l"(r) : "f"(a), "f"(b)); return r;
}
__device__ __forceinline__ void up(u64 v, float& a, float& b) {
    asm("mov.b64 {%0, %1}, %2;" : "=f"(a), "=f"(b) : "l"(v));
}
__device__ __forceinline__ float hsum2(u64 v) { float a, b; up(v, a, b); return a + b; }

__global__ void prep_kernel(const float* __restrict__ w1,
                            const float* __restrict__ gw,
                            const float* __restrict__ w2) {
    int idx = blockIdx.x * 256 + threadIdx.x;
    if (idx < 49152) {
        int l = idx >> 14, r = idx & 16383;
        int c4 = r >> 9, r2 = r & 511, h = r2 >> 2, q = r2 & 3;
        w1q_d[idx] = w1[(l * 128 + h) * 128 + c4 * 4 + q];
    } else if (idx < 98304) {
        int k = idx - 49152;
        int l = k >> 14, r = k & 16383;
        int h4 = r >> 9, r2 = r & 511, c = r2 >> 2, q = r2 & 3;
        w2q_d[k] = w2[(l * 128 + c) * 128 + h4 * 4 + q];
    } else if (idx < 131072) {
        int k = idx - 98304;
        int hp = k >> 9, s = (k >> 8) & 1, jb = (k >> 2) & 63, q = k & 3;
        int o = (q < 2) ? (2 * jb + q) : (128 + 2 * jb + (q - 2));
        gwQ_d[k] = gw[o * 128 + 2 * hp + s];
    }
}

// ---- smem byte offsets (one 512-thread CTA / SM, persistent) ----
#define SM_WQ    0         // 131072  SwiGLU weights [hp][s][jb][4]
#define SM_SP    131072    // 18432   4 x 1152 f : packed/normalized p ; later h2
#define SM_SH    149504    // 18432   4 x 1152 f : h1
#define SM_GP    167936    // 25600   gP[hp][50 u64]
#define SM_G2    193536    // 24960   g2N[48][65 u64]
#define SM_TGT   218496    // 504 f
#define SM_FGT   220512    // 504 f
#define SM_NW    222528    // 384 f
#define SM_B1    224064    // 128 f
#define SM_B2    224576    // 128 f
#define SM_RED   225088    // 64 f
#define SM_TOTAL 225344

// single-stream linear run with 4-deep weight prefetch
template<int CNT, bool BIAS, bool ISL2>
__device__ __forceinline__ void lin_run(int l, int m0, int hc,
        const float* sP, float* sH, const float* s_bias,
        float* __restrict__ y, long long n0, int Nn) {
    const float* wsrc = ISL2 ? w2q_d : w1q_d;
    const float4* wr = ((const float4*)wsrc) + l * 4096 + hc;
    float4 wb[4];
    #pragma unroll
    for (int j = 0; j < 4; ++j) wb[j] = wr[j * 128];
    u64 a0[CNT][4], a1[CNT][4];
    #pragma unroll
    for (int i = 0; i < CNT; ++i)
        #pragma unroll
        for (int nb = 0; nb < 4; ++nb) { a0[i][nb] = 0ull; a1[i][nb] = 0ull; }
    #pragma unroll
    for (int c4 = 0; c4 < 32; ++c4) {
        float4 w4 = wb[c4 & 3];
        if (c4 < 28) wb[c4 & 3] = wr[(c4 + 4) * 128];
        u64 wxy = pk(w4.x, w4.y), wzw = pk(w4.z, w4.w);
        #pragma unroll
        for (int i = 0; i < CNT; ++i)
            #pragma unroll
            for (int nb = 0; nb < 4; ++nb) {
                float4 p4 = ((const float4*)(sP + nb * 1152 + (m0 + i) * 128))[c4];
                a0[i][nb] = fma2(pk(p4.x, p4.y), wxy, a0[i][nb]);
                a1[i][nb] = fma2(pk(p4.z, p4.w), wzw, a1[i][nb]);
            }
    }
    #pragma unroll
    for (int i = 0; i < CNT; ++i) {
        int m = m0 + i;
        #pragma unroll
        for (int nb = 0; nb < 4; ++nb) {
            float r = hsum2(a0[i][nb]) + hsum2(a1[i][nb]);
            if (BIAS) r += s_bias[hc];
            if (ISL2) {
                int pidx;
                if (m == 0)      pidx = hc;
                else if (m < 4)  pidx = 128 + hc * 3 + (m - 1);
                else             pidx = 512 + hc * 5 + (m - 4);
                long long node = n0 + nb; if (node >= Nn) node = Nn - 1;
                y[node * 1152 + pidx] = r;
            } else {
                sH[nb * 1152 + m * 128 + hc] = r;
            }
        }
    }
}

// dual-stream run: two (l, m) single-m streams prefetched concurrently (MLP 8)
template<bool BIASA, bool ISL2>
__device__ __forceinline__ void lin_dual(int la, int ma, int lb, int mb, int hc,
        const float* sP, float* sH, const float* s_bias,
        float* __restrict__ y, long long n0, int Nn) {
    const float* wsrc = ISL2 ? w2q_d : w1q_d;
    const float4* wra = ((const float4*)wsrc) + la * 4096 + hc;
    const float4* wrb = ((const float4*)wsrc) + lb * 4096 + hc;
    float4 wba[4], wbb[4];
    #pragma unroll
    for (int j = 0; j < 4; ++j) { wba[j] = wra[j * 128]; wbb[j] = wrb[j * 128]; }
    u64 aa0[4], aa1[4], ab0[4], ab1[4];
    #pragma unroll
    for (int nb = 0; nb < 4; ++nb) { aa0[nb] = aa1[nb] = ab0[nb] = ab1[nb] = 0ull; }
    #pragma unroll
    for (int c4 = 0; c4 < 32; ++c4) {
        float4 wa = wba[c4 & 3], wcb = wbb[c4 & 3];
        if (c4 < 28) { wba[c4 & 3] = wra[(c4 + 4) * 128]; wbb[c4 & 3] = wrb[(c4 + 4) * 128]; }
        u64 waxy = pk(wa.x, wa.y), wazw = pk(wa.z, wa.w);
        u64 wbxy = pk(wcb.x, wcb.y), wbzw = pk(wcb.z, wcb.w);
        #pragma unroll
        for (int nb = 0; nb < 4; ++nb) {
            float4 pa = ((const float4*)(sP + nb * 1152 + ma * 128))[c4];
            float4 pb = ((const float4*)(sP + nb * 1152 + mb * 128))[c4];
            aa0[nb] = fma2(pk(pa.x, pa.y), waxy, aa0[nb]);
            aa1[nb] = fma2(pk(pa.z, pa.w), wazw, aa1[nb]);
            ab0[nb] = fma2(pk(pb.x, pb.y), wbxy, ab0[nb]);
            ab1[nb] = fma2(pk(pb.z, pb.w), wbzw, ab1[nb]);
        }
    }
    #pragma unroll
    for (int nb = 0; nb < 4; ++nb) {
        float ra = hsum2(aa0[nb]) + hsum2(aa1[nb]);
        float rb = hsum2(ab0[nb]) + hsum2(ab1[nb]);
        if (BIASA) ra += s_bias[hc];
        if (ISL2) {
            long long node = n0 + nb; if (node >= Nn) node = Nn - 1;
            int pa, pb;
            if (ma == 0)      pa = hc;
            else if (ma < 4)  pa = 128 + hc * 3 + (ma - 1);
            else              pa = 512 + hc * 5 + (ma - 4);
            if (mb < 4)       pb = 128 + hc * 3 + (mb - 1);
            else              pb = 512 + hc * 5 + (mb - 4);
            y[node * 1152 + pa] = ra;
            y[node * 1152 + pb] = rb;
        } else {
            sH[nb * 1152 + ma * 128 + hc] = ra;
            sH[nb * 1152 + mb * 128 + hc] = rb;
        }
    }
}

// toGrid for one node: thread (t_a, t_hp0) writes gP[hp][a] h-pair u64s
__device__ __forceinline__ void togrid_node(const float* sHn, float* gP,
        const float* s_tgT, int t_a, int t_hp0) {
    const float4* tgp = (const float4*)(s_tgT + t_a * 12);
    float4 f0 = tgp[0], f1 = tgp[1];
    float f8 = s_tgT[t_a * 12 + 8];
    u64 t0 = pk(f0.x, f0.x), t1 = pk(f0.y, f0.y), t2 = pk(f0.z, f0.z);
    u64 t3 = pk(f0.w, f0.w), t4 = pk(f1.x, f1.x), t5 = pk(f1.y, f1.y);
    u64 t6 = pk(f1.z, f1.z), t7 = pk(f1.w, f1.w), t8 = pk(f8, f8);
    const u64* hr0 = (const u64*)sHn;
    for (int hp = t_hp0; hp < 64; hp += 12) {
        const u64* hr = hr0 + hp;
        u64 acc0, acc1;
        acc0 = fma2(hr[0], t0, 0ull);
        acc1 = fma2(hr[64], t1, 0ull);
        acc0 = fma2(hr[128], t2, acc0);
        acc1 = fma2(hr[192], t3, acc1);
        acc0 = fma2(hr[256], t4, acc0);
        acc1 = fma2(hr[320], t5, acc1);
        acc0 = fma2(hr[384], t6, acc0);
        acc1 = fma2(hr[448], t7, acc1);
        acc0 = fma2(hr[512], t8, acc0);
        ((u64*)gP)[hp * 50 + t_a] = add2(acc0, acc1);
    }
}

__global__ __launch_bounds__(512, 1) void fused_kernel(
    const float* __restrict__ x,
    const float* __restrict__ nw,
    const float* __restrict__ b1,
    const float* __restrict__ gb,
    const float* __restrict__ b2,
    const float* __restrict__ tg,
    const float* __restrict__ fg,
    float* __restrict__ y, int Nn, int ntiles)
{
    extern __shared__ char smx[];
    float* sWQ   = (float*)(smx + SM_WQ);
    float* sP    = (float*)(smx + SM_SP);
    float* sH    = (float*)(smx + SM_SH);
    float* gP    = (float*)(smx + SM_GP);
    float* g2f   = (float*)(smx + SM_G2);
    float* s_tgT = (float*)(smx + SM_TGT);
    float* s_fgT = (float*)(smx + SM_FGT);
    float* s_nw  = (float*)(smx + SM_NW);
    float* s_b1  = (float*)(smx + SM_B1);
    float* s_b2  = (float*)(smx + SM_B2);
    float* sRed  = (float*)(smx + SM_RED);

    const int tid = threadIdx.x;
    const int wid = tid >> 5, lane = tid & 31;

    // SwiGLU coords: warps 2(a) x 8(jb); thread 6a x 1 o-pair-column (gate+value)
    const int s_a0 = (wid >> 3) * 24 + (lane >> 3) * 6;   // [0,48), even
    const int s_jb = (wid & 7) * 8 + (lane & 7);          // [0,64)
    const u64 gbg = pk(__ldg(gb + 2 * s_jb), __ldg(gb + 2 * s_jb + 1));
    const u64 gbv = pk(__ldg(gb + 128 + 2 * s_jb), __ldg(gb + 128 + 2 * s_jb + 1));
    // toGrid coords
    const int t_a = (tid < 504) ? (tid % 42) : 0;
    const int t_hp0 = (tid < 504) ? (tid / 42) : 64;

    // stage constants + resident SwiGLU weights (once per CTA)
    for (int j = tid; j < 378; j += THREADS) {
        int a = j / 9, m = j - a * 9;
        s_tgT[a * 12 + m] = tg[j];
        s_fgT[a * 12 + m] = fg[m * 42 + a];
    }
    for (int j = tid; j < 384; j += THREADS) s_nw[j] = nw[j];
    if (tid < 128) { s_b1[tid] = b1[tid]; s_b2[tid] = b2[tid]; }
    {
        const float4* src = (const float4*)gwQ_d;
        float4* dst = (float4*)sWQ;
        for (int j = tid; j < 8192; j += THREADS) dst[j] = src[j];
    }
    __syncthreads();

    for (int tile = blockIdx.x; tile < ntiles; tile += gridDim.x) {
        const long long n0 = (long long)tile * 4;

        // ---- pack + sum of squares, 4 nodes ----
        float ss[4] = {0.f, 0.f, 0.f, 0.f};
        #pragma unroll
        for (int nb = 0; nb < 4; ++nb) {
            long long node = n0 + nb; if (node >= Nn) node = Nn - 1;
            const float4* xr4 = (const float4*)(x + node * 1152);
            float* sPn = sP + nb * 1152;
            for (int j4 = tid; j4 < 288; j4 += THREADS) {
                float4 v4 = xr4[j4];
                int jb = j4 * 4;
                float vv[4] = {v4.x, v4.y, v4.z, v4.w};
                #pragma unroll
                for (int k = 0; k < 4; ++k) {
                    int j = jb + k;
                    float v = vv[k];
                    ss[nb] += v * v;
                    int m, c;
                    if (j < 128)      { m = 0; c = j; }
                    else if (j < 512) { int u = j - 128; c = u / 3; m = 1 + (u - c * 3); }
                    else              { int u = j - 512; c = u / 5; m = 4 + (u - c * 5); }
                    sPn[m * 128 + c] = v;
                }
            }
        }
        #pragma unroll
        for (int nb = 0; nb < 4; ++nb) {
            float s = ss[nb];
            #pragma unroll
            for (int off = 16; off; off >>= 1) s += __shfl_xor_sync(0xffffffffu, s, off);
            if (lane == 0) sRed[nb * 16 + wid] = s;
        }
        __syncthreads();
        {
            float inv[4];
            #pragma unroll
            for (int nb = 0; nb < 4; ++nb) {
                float tot = 0.f;
                #pragma unroll
                for (int w = 0; w < 16; ++w) tot += sRed[nb * 16 + w];
                inv[nb] = 1.0f / sqrtf(tot * (1.0f / 1152.0f) + 1e-6f);
            }
            for (int j = tid; j < 1152; j += THREADS) {
                int m = j >> 7, c = j & 127;
                int l = (m > 0) + (m > 3);
                float s = s_nw[l * 128 + c];
                #pragma unroll
                for (int nb = 0; nb < 4; ++nb) sP[nb * 1152 + j] *= inv[nb] * s;
            }
        }
        __syncthreads();

        // ---- SO3Linear #1 (prefetched streams) ----
        {
            const int h = tid & 127, sel = tid >> 7;
            if (sel == 0)      lin_dual<true,  false>(0, 0, 2, 4, h, sP, sH, s_b1, y, n0, Nn);
            else if (sel == 1) lin_run<2, false, false>(1, 1, h, sP, sH, s_b1, y, n0, Nn);
            else if (sel == 2) lin_dual<false, false>(1, 3, 2, 5, h, sP, sH, s_b1, y, n0, Nn);
            else               lin_run<3, false, false>(2, 6, h, sP, sH, s_b1, y, n0, Nn);
        }
        __syncthreads();

        // ---- toGrid(0) ----
        if (tid < 504) togrid_node(sH, gP, s_tgT, t_a, t_hp0);
        __syncthreads();

        // ---- per-node: SwiGLU(nb) | merged { toGrid(nb+1) + fromGrid(nb) } ----
        #pragma unroll 1
        for (int nb = 0; nb < 4; ++nb) {
            // -- SwiGLU: smem-resident weights, thread-local gating --
            {
                u64 zg[6], zv[6];
                #pragma unroll
                for (int i = 0; i < 6; ++i) { zg[i] = 0ull; zv[i] = 0ull; }
                const float4* wq0 = ((const float4*)sWQ) + s_jb;
                const float4* wq1 = wq0 + 64;
                #pragma unroll 2
                for (int hp = 0; hp < 64; ++hp) {
                    const float4* gvp = (const float4*)(gP + hp * 100) + (s_a0 >> 1);
                    float4 G0 = gvp[0], G1 = gvp[1], G2 = gvp[2];
                    float4 q0 = wq0[hp * 128];
                    float4 q1 = wq1[hp * 128];
                    u64 wg0 = pk(q0.x, q0.y), wv0 = pk(q0.z, q0.w);
                    u64 wg1 = pk(q1.x, q1.y), wv1 = pk(q1.z, q1.w);
                    float ga0[6] = {G0.x, G0.z, G1.x, G1.z, G2.x, G2.z};
                    float ga1[6] = {G0.y, G0.w, G1.y, G1.w, G2.y, G2.w};
                    #pragma unroll
                    for (int i = 0; i < 6; ++i) {
                        u64 d0 = pk(ga0[i], ga0[i]);
                        u64 d1 = pk(ga1[i], ga1[i]);
                        zg[i] = fma2(d0, wg0, zg[i]);
                        zv[i] = fma2(d0, wv0, zv[i]);
                        zg[i] = fma2(d1, wg1, zg[i]);
                        zv[i] = fma2(d1, wv1, zv[i]);
                    }
                }
                #pragma unroll
                for (int i = 0; i < 6; ++i) {
                    u64 zgb = add2(zg[i], gbg);
                    u64 zvb = add2(zv[i], gbv);
                    float g0, g1, v0, v1;
                    up(zgb, g0, g1); up(zvb, v0, v1);
                    float r0 = (g0 / (1.0f + __expf(-g0))) * v0;
                    float r1 = (g1 / (1.0f + __expf(-g1))) * v1;
                    ((u64*)g2f)[(s_a0 + i) * 65 + s_jb] = pk(r0, r1);
                }
            }
            __syncthreads();

            // -- merged: toGrid(nb+1) -> gP  +  fromGrid(nb) -> sP[nb] --
            if (nb + 1 < 4 && tid < 504)
                togrid_node(sH + (nb + 1) * 1152, gP, s_tgT, t_a, t_hp0);
            for (int s = tid; s < 576; s += THREADS) {
                int m = s >> 6, hp = s & 63;
                const u64* g2 = ((const u64*)g2f) + hp;
                u64 am0 = 0ull, am1 = 0ull;
                #pragma unroll 2
                for (int a = 0; a < 42; a += 2) {
                    float fa = s_fgT[a * 12 + m];
                    float fb = s_fgT[(a + 1) * 12 + m];
                    am0 = fma2(g2[a * 65], pk(fa, fa), am0);
                    am1 = fma2(g2[(a + 1) * 65], pk(fb, fb), am1);
                }
                ((u64*)(sP + nb * 1152 + m * 128))[hp] = add2(am0, am1);
            }
            __syncthreads();
        }

        // ---- SO3Linear #2 + unpack store (prefetched streams) ----
        {
            const int c = tid & 127, sel = tid >> 7;
            if (sel == 0)      lin_dual<true,  true>(0, 0, 2, 4, c, sP, sH, s_b2, y, n0, Nn);
            else if (sel == 1) lin_run<2, false, true>(1, 1, c, sP, sH, s_b2, y, n0, Nn);
            else if (sel == 2) lin_dual<false, true>(1, 3, 2, 5, c, sP, sH, s_b2, y, n0, Nn);
            else               lin_run<3, false, true>(2, 6, c, sP, sH, s_b2, y, n0, Nn);
        }
        __syncthreads();
    }
}

extern "C" void kernel_launch(void* const* d_in, const int* in_sizes, int n_in,
                              void* d_out, int out_size) {
    const float* x  = (const float*)d_in[0];
    const float* nw = (const float*)d_in[1];
    const float* w1 = (const float*)d_in[2];
    const float* b1 = (const float*)d_in[3];
    const float* gw = (const float*)d_in[4];
    const float* gb = (const float*)d_in[5];
    const float* w2 = (const float*)d_in[6];
    const float* b2 = (const float*)d_in[7];
    const float* tg = (const float*)d_in[8];
    const float* fg = (const float*)d_in[9];
    float* y = (float*)d_out;

    int N = in_sizes[0] / 1152;
    int ntiles = (N + 3) / 4;
    int grid = ntiles < 148 ? ntiles : 148;

    prep_kernel<<<512, 256>>>(w1, gw, w2);

    cudaFuncSetAttribute(fused_kernel, cudaFuncAttributeMaxDynamicSharedMemorySize,
                         SM_TOTAL);
    fused_kernel<<<grid, THREADS, SM_TOTAL>>>(x, nw, b1, gb, b2, tg, fg, y, N, ntiles);
}